// round 5
// baseline (speedup 1.0000x reference)
#include <cuda_runtime.h>
#include <math.h>
#include <stdint.h>

#define BB 4
#define TT 4096
#define CC 2048
#define HH 128
#define NROW (BB * TT)          // 16384

// Scratch for Q, K, V projections: [B*T, H] each, fp32.
__device__ float g_q[NROW * HH];
__device__ float g_k[NROW * HH];
__device__ float g_v[NROW * HH];

// ---------------------------------------------------------------------------
// tf32 helpers
// ---------------------------------------------------------------------------
__device__ __forceinline__ float ftf32(float x) {
    uint32_t u;
    asm("cvt.rna.tf32.f32 %0, %1;" : "=r"(u) : "f"(x));
    return __uint_as_float(u);
}

__device__ __forceinline__ void mma_tf32(float* d, const float* a, const float* b) {
    asm volatile(
        "mma.sync.aligned.m16n8k8.row.col.f32.tf32.tf32.f32 "
        "{%0,%1,%2,%3}, {%4,%5,%6,%7}, {%8,%9}, {%0,%1,%2,%3};"
        : "+f"(d[0]), "+f"(d[1]), "+f"(d[2]), "+f"(d[3])
        : "r"(__float_as_uint(a[0])), "r"(__float_as_uint(a[1])),
          "r"(__float_as_uint(a[2])), "r"(__float_as_uint(a[3])),
          "r"(__float_as_uint(b[0])), "r"(__float_as_uint(b[1])));
}

// ---------------------------------------------------------------------------
// Kernel 1: fused QKV projection.  Out[row, h] = sum_k idx[row,k] * W[h,k]
// BM=128 rows, BN=128 (all H), BK=32.  256 threads = 8 warps (4x2 warp grid:
// each warp 32 rows x 64 cols of output via m16n8k8 tf32 mma).
// grid = (128 row tiles, 3 weights)
// ---------------------------------------------------------------------------
#define QBK 32
#define QKS 36      // smem k-stride (floats): (36*m + k) % 32 == 4*grp+lq -> conflict free

__global__ __launch_bounds__(256, 2)
void qkv_kernel(const float* __restrict__ idx,
                const float* __restrict__ Wq,
                const float* __restrict__ Wk,
                const float* __restrict__ Wv)
{
    __shared__ float As[128][QKS];   // A tile, row-major [m][k]
    __shared__ float Bs[128][QKS];   // W tile, row-major [n][k]

    const int w = blockIdx.y;
    const float* __restrict__ Wp = (w == 0) ? Wq : (w == 1) ? Wk : Wv;
    float* __restrict__ Out = (w == 0) ? g_q : (w == 1) ? g_k : g_v;

    const int row0 = blockIdx.x * 128;
    const int tid  = threadIdx.x;
    const int warp = tid >> 5, lane = tid & 31;
    const int grp  = lane >> 2, lq = lane & 3;
    const int wm   = warp >> 1;          // 0..3 -> m base wm*32 (2 m16 tiles)
    const int wn   = warp & 1;           // 0..1 -> n base wn*64 (8 n8 tiles)

    float acc[2][8][4];
#pragma unroll
    for (int mt = 0; mt < 2; mt++)
#pragma unroll
        for (int nt = 0; nt < 8; nt++)
#pragma unroll
            for (int r = 0; r < 4; r++) acc[mt][nt][r] = 0.f;

    for (int k0 = 0; k0 < CC; k0 += QBK) {
        // Load A (128x32) and B (128x32), tf32-rounded, row-major smem.
#pragma unroll
        for (int i = 0; i < 4; i++) {
            int fi = tid + 256 * i;          // float4 index 0..1023
            int m  = fi >> 3;                // 0..127
            int kq = (fi & 7) * 4;           // 0..28
            float4 va = *(const float4*)(idx + (size_t)(row0 + m) * CC + k0 + kq);
            float4 ta = make_float4(ftf32(va.x), ftf32(va.y), ftf32(va.z), ftf32(va.w));
            *(float4*)&As[m][kq] = ta;
            float4 vb = *(const float4*)(Wp + (size_t)m * CC + k0 + kq);
            float4 tb = make_float4(ftf32(vb.x), ftf32(vb.y), ftf32(vb.z), ftf32(vb.w));
            *(float4*)&Bs[m][kq] = tb;
        }
        __syncthreads();

#pragma unroll
        for (int kk = 0; kk < 4; kk++) {
            const int kb = kk * 8;
            float a[2][4], b[8][2];
#pragma unroll
            for (int mt = 0; mt < 2; mt++) {
                int m = wm * 32 + mt * 16 + grp;
                a[mt][0] = As[m][kb + lq];
                a[mt][1] = As[m + 8][kb + lq];
                a[mt][2] = As[m][kb + lq + 4];
                a[mt][3] = As[m + 8][kb + lq + 4];
            }
#pragma unroll
            for (int nt = 0; nt < 8; nt++) {
                int n = wn * 64 + nt * 8 + grp;
                b[nt][0] = Bs[n][kb + lq];
                b[nt][1] = Bs[n][kb + lq + 4];
            }
#pragma unroll
            for (int mt = 0; mt < 2; mt++)
#pragma unroll
                for (int nt = 0; nt < 8; nt++)
                    mma_tf32(acc[mt][nt], a[mt], b[nt]);
        }
        __syncthreads();
    }

#pragma unroll
    for (int mt = 0; mt < 2; mt++)
#pragma unroll
        for (int nt = 0; nt < 8; nt++) {
            int r = row0 + wm * 32 + mt * 16 + grp;
            int c = wn * 64 + nt * 8 + 2 * lq;
            *(float2*)&Out[(size_t)r * HH + c] =
                make_float2(acc[mt][nt][0], acc[mt][nt][1]);
            *(float2*)&Out[(size_t)(r + 8) * HH + c] =
                make_float2(acc[mt][nt][2], acc[mt][nt][3]);
        }
}

// ---------------------------------------------------------------------------
// Kernel 2: causal attention, flash style, tf32 mma.
// S[i,j] = scale * <k_i, q_j>, softmax over j<=i, O[i,:] = sum_j P[i,j] v_j.
// CTA: 64 i-rows resident (K tile), loops 64-wide j-tiles of Q/V.
// Persistent pairing: each CTA handles i-blocks (p, 63-p) -> 65 j-iters each.
// 256 threads = 8 warps; warp grid 4x2.
// S phase: warp tile m16 x n32.  PV phase: warp tile m16 x n64 (h).
// ---------------------------------------------------------------------------
#define AM 64
#define AN 64
#define KQS 132     // K/Q smem h-stride
#define VST 68      // Vt / Ss smem stride

#define ATTN_SMEM_FLOATS (2 * AM * KQS + HH * VST + AM * VST + 3 * AM)
#define ATTN_SMEM_BYTES  (ATTN_SMEM_FLOATS * 4)

__global__ __launch_bounds__(256, 1)
void attn_kernel(float* __restrict__ out)
{
    extern __shared__ float sm[];
    float* Ks  = sm;                       // [64][132]  K rows (tf32)
    float* Qs  = Ks + AM * KQS;            // [64][132]  Q rows (tf32)
    float* Vt  = Qs + AM * KQS;            // [128][68]  V transposed [h][j] (tf32)
    float* Ss  = Vt + HH * VST;            // [64][68]   scores / probs
    float* m_s = Ss + AM * VST;            // [64]
    float* l_s = m_s + AM;                 // [64]
    float* a_s = l_s + AM;                 // [64]

    const int b    = blockIdx.y;
    const int pair = blockIdx.x;           // 0..31
    const int tid  = threadIdx.x;
    const int warp = tid >> 5, lane = tid & 31;
    const int grp  = lane >> 2, lq = lane & 3;
    const int wm   = warp >> 1;            // m16 tile: rows wm*16
    const int wn   = warp & 1;

    const float scale = rsqrtf((float)CC);

    for (int phase = 0; phase < 2; phase++) {
        const int ib = (phase == 0) ? pair : 63 - pair;
        const int i0 = ib * AM;

        // Load resident K tile (tf32-rounded)
        const float* kbase = g_k + ((size_t)b * TT + i0) * HH;
#pragma unroll
        for (int i = 0; i < 8; i++) {
            int fi = tid + 256 * i;          // 2048 float4
            int r  = fi >> 5;                // 0..63
            int c  = (fi & 31) * 4;          // 0..124
            float4 v = *(const float4*)(kbase + r * HH + c);
            *(float4*)&Ks[r * KQS + c] =
                make_float4(ftf32(v.x), ftf32(v.y), ftf32(v.z), ftf32(v.w));
        }
        if (tid < AM) { m_s[tid] = -INFINITY; l_s[tid] = 0.f; }

        float o[8][4];                       // m16 x n64 (8 n8 tiles)
#pragma unroll
        for (int nt = 0; nt < 8; nt++)
#pragma unroll
            for (int r = 0; r < 4; r++) o[nt][r] = 0.f;
        __syncthreads();

        for (int jb = 0; jb <= ib; jb++) {
            const int j0 = jb * AN;
            const float* qb = g_q + ((size_t)b * TT + j0) * HH;
            const float* vb = g_v + ((size_t)b * TT + j0) * HH;
#pragma unroll
            for (int i = 0; i < 8; i++) {
                int fi = tid + 256 * i;
                int r  = fi >> 5;
                int c  = (fi & 31) * 4;
                float4 vq = *(const float4*)(qb + r * HH + c);
                *(float4*)&Qs[r * KQS + c] =
                    make_float4(ftf32(vq.x), ftf32(vq.y), ftf32(vq.z), ftf32(vq.w));
                float4 vv = *(const float4*)(vb + r * HH + c);
                Vt[(c + 0) * VST + r] = ftf32(vv.x);
                Vt[(c + 1) * VST + r] = ftf32(vv.y);
                Vt[(c + 2) * VST + r] = ftf32(vv.z);
                Vt[(c + 3) * VST + r] = ftf32(vv.w);
            }
            __syncthreads();

            // ---- S = Ks . Qs^T : warp tile m16 (rows wm*16) x n32 (cols wn*32)
            float sfr[4][4];
#pragma unroll
            for (int nt = 0; nt < 4; nt++)
#pragma unroll
                for (int r = 0; r < 4; r++) sfr[nt][r] = 0.f;

            const int mrow = wm * 16 + grp;
#pragma unroll
            for (int kk = 0; kk < 16; kk++) {
                const int kb = kk * 8;
                float a[4], bq[4][2];
                a[0] = Ks[mrow * KQS + kb + lq];
                a[1] = Ks[(mrow + 8) * KQS + kb + lq];
                a[2] = Ks[mrow * KQS + kb + lq + 4];
                a[3] = Ks[(mrow + 8) * KQS + kb + lq + 4];
#pragma unroll
                for (int nt = 0; nt < 4; nt++) {
                    int n = wn * 32 + nt * 8 + grp;
                    bq[nt][0] = Qs[n * KQS + kb + lq];
                    bq[nt][1] = Qs[n * KQS + kb + lq + 4];
                }
#pragma unroll
                for (int nt = 0; nt < 4; nt++) mma_tf32(sfr[nt], a, bq[nt]);
            }

            // scale + causal mask + store to Ss
#pragma unroll
            for (int nt = 0; nt < 4; nt++) {
                int c = wn * 32 + nt * 8 + 2 * lq;
                int r = wm * 16 + grp;
                float v0 = sfr[nt][0] * scale, v1 = sfr[nt][1] * scale;
                float v2 = sfr[nt][2] * scale, v3 = sfr[nt][3] * scale;
                if (jb == ib) {              // diagonal tile: mask j > i
                    if (c > r)         v0 = -INFINITY;
                    if (c + 1 > r)     v1 = -INFINITY;
                    if (c > r + 8)     v2 = -INFINITY;
                    if (c + 1 > r + 8) v3 = -INFINITY;
                }
                *(float2*)&Ss[r * VST + c]       = make_float2(v0, v1);
                *(float2*)&Ss[(r + 8) * VST + c] = make_float2(v2, v3);
            }
            __syncthreads();

            // ---- online softmax: 4 threads per row, 16 cols each
            {
                const int row = tid >> 2;
                const int q4  = tid & 3;
                float* srow = Ss + row * VST + q4 * 16;
                float mx = -INFINITY;
#pragma unroll
                for (int c = 0; c < 16; c++) mx = fmaxf(mx, srow[c]);
                mx = fmaxf(mx, __shfl_xor_sync(0xffffffffu, mx, 1));
                mx = fmaxf(mx, __shfl_xor_sync(0xffffffffu, mx, 2));
                const float m_old = m_s[row];
                const float m_new = fmaxf(m_old, mx);
                float ps = 0.f;
#pragma unroll
                for (int c = 0; c < 16; c++) {
                    float p = __expf(srow[c] - m_new);
                    ps += p;
                    srow[c] = ftf32(p);      // P consumed by tf32 mma
                }
                ps += __shfl_xor_sync(0xffffffffu, ps, 1);
                ps += __shfl_xor_sync(0xffffffffu, ps, 2);
                if (q4 == 0) {
                    const float al = __expf(m_old - m_new);
                    a_s[row] = al;
                    l_s[row] = l_s[row] * al + ps;
                    m_s[row] = m_new;
                }
            }
            __syncthreads();

            // ---- O = O*alpha + P @ V : warp tile m16 x n64 (cols wn*64)
            {
                const float al0 = a_s[mrow];
                const float al1 = a_s[mrow + 8];
#pragma unroll
                for (int nt = 0; nt < 8; nt++) {
                    o[nt][0] *= al0; o[nt][1] *= al0;
                    o[nt][2] *= al1; o[nt][3] *= al1;
                }
#pragma unroll
                for (int kk = 0; kk < 8; kk++) {
                    const int kb = kk * 8;
                    float a[4], bv[8][2];
                    a[0] = Ss[mrow * VST + kb + lq];
                    a[1] = Ss[(mrow + 8) * VST + kb + lq];
                    a[2] = Ss[mrow * VST + kb + lq + 4];
                    a[3] = Ss[(mrow + 8) * VST + kb + lq + 4];
#pragma unroll
                    for (int nt = 0; nt < 8; nt++) {
                        int n = wn * 64 + nt * 8 + grp;   // h index
                        bv[nt][0] = Vt[n * VST + kb + lq];
                        bv[nt][1] = Vt[n * VST + kb + lq + 4];
                    }
#pragma unroll
                    for (int nt = 0; nt < 8; nt++) mma_tf32(o[nt], a, bv[nt]);
                }
            }
            __syncthreads();   // protect Qs/Vt/Ss before next tile load
        }

        // ---- epilogue: divide by l, write out
        const int mrow = wm * 16 + grp;
        const float inv0 = 1.f / l_s[mrow];
        const float inv1 = 1.f / l_s[mrow + 8];
        float* obase = out + ((size_t)b * TT + i0) * HH;
#pragma unroll
        for (int nt = 0; nt < 8; nt++) {
            int c = wn * 64 + nt * 8 + 2 * lq;
            *(float2*)&obase[(size_t)mrow * HH + c] =
                make_float2(o[nt][0] * inv0, o[nt][1] * inv0);
            *(float2*)&obase[(size_t)(mrow + 8) * HH + c] =
                make_float2(o[nt][2] * inv1, o[nt][3] * inv1);
        }
        __syncthreads();   // all done with smem before next phase reloads
    }
}

// ---------------------------------------------------------------------------
extern "C" void kernel_launch(void* const* d_in, const int* in_sizes, int n_in,
                              void* d_out, int out_size)
{
    const float* idx = (const float*)d_in[0];
    const float* Wq  = (const float*)d_in[1];
    const float* Wk  = (const float*)d_in[2];
    const float* Wv  = (const float*)d_in[3];
    float* out = (float*)d_out;

    cudaFuncSetAttribute(attn_kernel,
                         cudaFuncAttributeMaxDynamicSharedMemorySize,
                         ATTN_SMEM_BYTES);

    qkv_kernel<<<dim3(NROW / 128, 3), 256>>>(idx, Wq, Wk, Wv);
    attn_kernel<<<dim3(32, BB), 256, ATTN_SMEM_BYTES>>>(out);
}

// round 6
// speedup vs baseline: 1.2050x; 1.2050x over previous
#include <cuda_runtime.h>
#include <math.h>
#include <stdint.h>

#define BB 4
#define TT 4096
#define CC 2048
#define HH 128
#define NROW (BB * TT)          // 16384

// Scratch for Q, K, V projections: [B*T, H] each, fp32.
__device__ float g_q[NROW * HH];
__device__ float g_k[NROW * HH];
__device__ float g_v[NROW * HH];

// ---------------------------------------------------------------------------
// tf32 helpers
// ---------------------------------------------------------------------------
__device__ __forceinline__ float ftf32(float x) {
    uint32_t u;
    asm("cvt.rna.tf32.f32 %0, %1;" : "=r"(u) : "f"(x));
    return __uint_as_float(u);
}

__device__ __forceinline__ void mma_tf32(float* d, const float* a, const float* b) {
    asm volatile(
        "mma.sync.aligned.m16n8k8.row.col.f32.tf32.tf32.f32 "
        "{%0,%1,%2,%3}, {%4,%5,%6,%7}, {%8,%9}, {%0,%1,%2,%3};"
        : "+f"(d[0]), "+f"(d[1]), "+f"(d[2]), "+f"(d[3])
        : "r"(__float_as_uint(a[0])), "r"(__float_as_uint(a[1])),
          "r"(__float_as_uint(a[2])), "r"(__float_as_uint(a[3])),
          "r"(__float_as_uint(b[0])), "r"(__float_as_uint(b[1])));
}

// ---------------------------------------------------------------------------
// Kernel 1: fused QKV projection with register-prefetch pipeline.
// Out[row, h] = sum_k idx[row,k] * W[h,k].  BM=128, BN=128, BK=32.
// 256 threads = 8 warps (4x2), each warp m32 x n64 via m16n8k8 tf32 mma.
// ---------------------------------------------------------------------------
#define QBK 32
#define QKS 36

__global__ __launch_bounds__(256, 2)
void qkv_kernel(const float* __restrict__ idx,
                const float* __restrict__ Wq,
                const float* __restrict__ Wk,
                const float* __restrict__ Wv)
{
    __shared__ float As[128][QKS];
    __shared__ float Bs[128][QKS];

    const int w = blockIdx.y;
    const float* __restrict__ Wp = (w == 0) ? Wq : (w == 1) ? Wk : Wv;
    float* __restrict__ Out = (w == 0) ? g_q : (w == 1) ? g_k : g_v;

    const int row0 = blockIdx.x * 128;
    const int tid  = threadIdx.x;
    const int warp = tid >> 5, lane = tid & 31;
    const int grp  = lane >> 2, lq = lane & 3;
    const int wm   = warp >> 1;
    const int wn   = warp & 1;

    // per-thread load coords (same for A and B tiles)
    int lm[4], lk[4];
#pragma unroll
    for (int i = 0; i < 4; i++) {
        int fi = tid + 256 * i;
        lm[i] = fi >> 3;
        lk[i] = (fi & 7) * 4;
    }

    float4 ra[4], rb[4];
    // prologue: fetch tile k0=0
#pragma unroll
    for (int i = 0; i < 4; i++) {
        ra[i] = *(const float4*)(idx + (size_t)(row0 + lm[i]) * CC + lk[i]);
        rb[i] = *(const float4*)(Wp + (size_t)lm[i] * CC + lk[i]);
    }
#pragma unroll
    for (int i = 0; i < 4; i++) {
        *(float4*)&As[lm[i]][lk[i]] =
            make_float4(ftf32(ra[i].x), ftf32(ra[i].y), ftf32(ra[i].z), ftf32(ra[i].w));
        *(float4*)&Bs[lm[i]][lk[i]] =
            make_float4(ftf32(rb[i].x), ftf32(rb[i].y), ftf32(rb[i].z), ftf32(rb[i].w));
    }
    __syncthreads();

    float acc[2][8][4];
#pragma unroll
    for (int mt = 0; mt < 2; mt++)
#pragma unroll
        for (int nt = 0; nt < 8; nt++)
#pragma unroll
            for (int r = 0; r < 4; r++) acc[mt][nt][r] = 0.f;

    for (int k0 = 0; k0 < CC; k0 += QBK) {
        const int kn = k0 + QBK;
        if (kn < CC) {
#pragma unroll
            for (int i = 0; i < 4; i++) {
                ra[i] = *(const float4*)(idx + (size_t)(row0 + lm[i]) * CC + kn + lk[i]);
                rb[i] = *(const float4*)(Wp + (size_t)lm[i] * CC + kn + lk[i]);
            }
        }

#pragma unroll
        for (int kk = 0; kk < 4; kk++) {
            const int kb = kk * 8;
            float a[2][4], b[8][2];
#pragma unroll
            for (int mt = 0; mt < 2; mt++) {
                int m = wm * 32 + mt * 16 + grp;
                a[mt][0] = As[m][kb + lq];
                a[mt][1] = As[m + 8][kb + lq];
                a[mt][2] = As[m][kb + lq + 4];
                a[mt][3] = As[m + 8][kb + lq + 4];
            }
#pragma unroll
            for (int nt = 0; nt < 8; nt++) {
                int n = wn * 64 + nt * 8 + grp;
                b[nt][0] = Bs[n][kb + lq];
                b[nt][1] = Bs[n][kb + lq + 4];
            }
#pragma unroll
            for (int mt = 0; mt < 2; mt++)
#pragma unroll
                for (int nt = 0; nt < 8; nt++)
                    mma_tf32(acc[mt][nt], a[mt], b[nt]);
        }
        __syncthreads();

        if (kn < CC) {
#pragma unroll
            for (int i = 0; i < 4; i++) {
                *(float4*)&As[lm[i]][lk[i]] =
                    make_float4(ftf32(ra[i].x), ftf32(ra[i].y), ftf32(ra[i].z), ftf32(ra[i].w));
                *(float4*)&Bs[lm[i]][lk[i]] =
                    make_float4(ftf32(rb[i].x), ftf32(rb[i].y), ftf32(rb[i].z), ftf32(rb[i].w));
            }
            __syncthreads();
        }
    }

#pragma unroll
    for (int mt = 0; mt < 2; mt++)
#pragma unroll
        for (int nt = 0; nt < 8; nt++) {
            int r = row0 + wm * 32 + mt * 16 + grp;
            int c = wn * 64 + nt * 8 + 2 * lq;
            *(float2*)&Out[(size_t)r * HH + c] =
                make_float2(acc[mt][nt][0], acc[mt][nt][1]);
            *(float2*)&Out[(size_t)(r + 8) * HH + c] =
                make_float2(acc[mt][nt][2], acc[mt][nt][3]);
        }
}

// ---------------------------------------------------------------------------
// Kernel 2: causal attention, flash style, tf32 mma.
// S[i,j] = scale * <k_i, q_j>, softmax over j<=i, O[i,:] = sum_j P[i,j] v_j.
// CTA: 64 i-rows resident; j-tiles of width 128.
// 8 warps, warp grid 2(m) x 4(n): each warp m32 x n32 in both phases.
// Persistent pairing (p, 63-p) -> exactly 33 j-tiles per CTA.
// ---------------------------------------------------------------------------
#define AM 64
#define AN 128
#define TST 132     // universal smem stride

#define ATTN_SMEM_FLOATS ((AM + AN + HH + AM) * TST + 3 * AM)
#define ATTN_SMEM_BYTES  (ATTN_SMEM_FLOATS * 4)

__global__ __launch_bounds__(256, 1)
void attn_kernel(float* __restrict__ out)
{
    extern __shared__ float sm[];
    float* Ks  = sm;                       // [64][132]   K rows (tf32)
    float* Qs  = Ks + AM * TST;            // [128][132]  Q rows (tf32)
    float* Vt  = Qs + AN * TST;            // [128][132]  V transposed [h][j] (tf32)
    float* Ss  = Vt + HH * TST;            // [64][132]   scores / probs
    float* m_s = Ss + AM * TST;            // [64]
    float* l_s = m_s + AM;                 // [64]
    float* a_s = l_s + AM;                 // [64]

    const int b    = blockIdx.y;
    const int pair = blockIdx.x;           // 0..31
    const int tid  = threadIdx.x;
    const int warp = tid >> 5, lane = tid & 31;
    const int grp  = lane >> 2, lq = lane & 3;
    const int wm   = warp >> 2;            // 0..1 -> rows wm*32
    const int wn   = warp & 3;             // 0..3 -> cols wn*32

    const float scale = rsqrtf((float)CC);

    for (int phase = 0; phase < 2; phase++) {
        const int ib = (phase == 0) ? pair : 63 - pair;
        const int i0 = ib * AM;
        const int jt = ib >> 1;            // last j-tile index

        // Load resident K tile (tf32-rounded)
        const float* kbase = g_k + ((size_t)b * TT + i0) * HH;
#pragma unroll
        for (int i = 0; i < 8; i++) {
            int fi = tid + 256 * i;          // 2048 float4
            int r  = fi >> 5;
            int c  = (fi & 31) * 4;
            float4 v = *(const float4*)(kbase + r * HH + c);
            *(float4*)&Ks[r * TST + c] =
                make_float4(ftf32(v.x), ftf32(v.y), ftf32(v.z), ftf32(v.w));
        }
        if (tid < AM) { m_s[tid] = -INFINITY; l_s[tid] = 0.f; }

        float o[2][4][4];
#pragma unroll
        for (int mt = 0; mt < 2; mt++)
#pragma unroll
            for (int nt = 0; nt < 4; nt++)
#pragma unroll
                for (int r = 0; r < 4; r++) o[mt][nt][r] = 0.f;
        __syncthreads();

        for (int jb = 0; jb <= jt; jb++) {
            const int j0 = jb * AN;
            const float* qb = g_q + ((size_t)b * TT + j0) * HH;
            const float* vb = g_v + ((size_t)b * TT + j0) * HH;
#pragma unroll
            for (int i = 0; i < 16; i++) {
                int fi = tid + 256 * i;        // 4096 float4
                int r  = fi >> 5;              // 0..127 (j index)
                int c  = (fi & 31) * 4;        // 0..124 (h index)
                float4 vq = *(const float4*)(qb + r * HH + c);
                *(float4*)&Qs[r * TST + c] =
                    make_float4(ftf32(vq.x), ftf32(vq.y), ftf32(vq.z), ftf32(vq.w));
                float4 vv = *(const float4*)(vb + r * HH + c);
                Vt[(c + 0) * TST + r] = ftf32(vv.x);
                Vt[(c + 1) * TST + r] = ftf32(vv.y);
                Vt[(c + 2) * TST + r] = ftf32(vv.z);
                Vt[(c + 3) * TST + r] = ftf32(vv.w);
            }
            __syncthreads();

            // ---- S = Ks . Qs^T : warp m32 (rows wm*32) x n32 (cols wn*32) ----
            float sfr[2][4][4];
#pragma unroll
            for (int mt = 0; mt < 2; mt++)
#pragma unroll
                for (int nt = 0; nt < 4; nt++)
#pragma unroll
                    for (int r = 0; r < 4; r++) sfr[mt][nt][r] = 0.f;

#pragma unroll
            for (int kk = 0; kk < 16; kk++) {
                const int kb = kk * 8;
                float a[2][4], bq[4][2];
#pragma unroll
                for (int mt = 0; mt < 2; mt++) {
                    int m = wm * 32 + mt * 16 + grp;
                    a[mt][0] = Ks[m * TST + kb + lq];
                    a[mt][1] = Ks[(m + 8) * TST + kb + lq];
                    a[mt][2] = Ks[m * TST + kb + lq + 4];
                    a[mt][3] = Ks[(m + 8) * TST + kb + lq + 4];
                }
#pragma unroll
                for (int nt = 0; nt < 4; nt++) {
                    int n = wn * 32 + nt * 8 + grp;
                    bq[nt][0] = Qs[n * TST + kb + lq];
                    bq[nt][1] = Qs[n * TST + kb + lq + 4];
                }
#pragma unroll
                for (int mt = 0; mt < 2; mt++)
#pragma unroll
                    for (int nt = 0; nt < 4; nt++)
                        mma_tf32(sfr[mt][nt], a[mt], bq[nt]);
            }

            // scale + causal mask (global indices) + store to Ss
            const bool last = (jb == jt);
#pragma unroll
            for (int mt = 0; mt < 2; mt++)
#pragma unroll
                for (int nt = 0; nt < 4; nt++) {
                    int r = wm * 32 + mt * 16 + grp;
                    int c = wn * 32 + nt * 8 + 2 * lq;
                    float v0 = sfr[mt][nt][0] * scale, v1 = sfr[mt][nt][1] * scale;
                    float v2 = sfr[mt][nt][2] * scale, v3 = sfr[mt][nt][3] * scale;
                    if (last) {
                        int ig = i0 + r, jg = j0 + c;
                        if (jg > ig)         v0 = -INFINITY;
                        if (jg + 1 > ig)     v1 = -INFINITY;
                        if (jg > ig + 8)     v2 = -INFINITY;
                        if (jg + 1 > ig + 8) v3 = -INFINITY;
                    }
                    *(float2*)&Ss[r * TST + c]       = make_float2(v0, v1);
                    *(float2*)&Ss[(r + 8) * TST + c] = make_float2(v2, v3);
                }
            __syncthreads();

            // ---- online softmax: 4 threads/row, interleaved cols (bank-free)
            {
                const int row = tid >> 2;
                const int q4  = tid & 3;
                float* srow = Ss + row * TST;
                float mx = -INFINITY;
#pragma unroll
                for (int ci = 0; ci < 32; ci++)
                    mx = fmaxf(mx, srow[q4 + 4 * ci]);
                mx = fmaxf(mx, __shfl_xor_sync(0xffffffffu, mx, 1));
                mx = fmaxf(mx, __shfl_xor_sync(0xffffffffu, mx, 2));
                const float m_old = m_s[row];
                const float m_new = fmaxf(m_old, mx);
                float ps = 0.f;
#pragma unroll
                for (int ci = 0; ci < 32; ci++) {
                    float p = __expf(srow[q4 + 4 * ci] - m_new);
                    ps += p;
                    srow[q4 + 4 * ci] = ftf32(p);
                }
                ps += __shfl_xor_sync(0xffffffffu, ps, 1);
                ps += __shfl_xor_sync(0xffffffffu, ps, 2);
                if (q4 == 0) {
                    const float al = __expf(m_old - m_new);
                    a_s[row] = al;
                    l_s[row] = l_s[row] * al + ps;
                    m_s[row] = m_new;
                }
            }
            __syncthreads();

            // ---- O = O*alpha + P @ V : warp m32 (rows) x n32 (h cols) ----
            {
                float al[2][2];
#pragma unroll
                for (int mt = 0; mt < 2; mt++) {
                    int m = wm * 32 + mt * 16 + grp;
                    al[mt][0] = a_s[m];
                    al[mt][1] = a_s[m + 8];
                }
#pragma unroll
                for (int mt = 0; mt < 2; mt++)
#pragma unroll
                    for (int nt = 0; nt < 4; nt++) {
                        o[mt][nt][0] *= al[mt][0]; o[mt][nt][1] *= al[mt][0];
                        o[mt][nt][2] *= al[mt][1]; o[mt][nt][3] *= al[mt][1];
                    }
#pragma unroll
                for (int kk = 0; kk < 16; kk++) {
                    const int kb = kk * 8;
                    float a[2][4], bv[4][2];
#pragma unroll
                    for (int mt = 0; mt < 2; mt++) {
                        int m = wm * 32 + mt * 16 + grp;
                        a[mt][0] = Ss[m * TST + kb + lq];
                        a[mt][1] = Ss[(m + 8) * TST + kb + lq];
                        a[mt][2] = Ss[m * TST + kb + lq + 4];
                        a[mt][3] = Ss[(m + 8) * TST + kb + lq + 4];
                    }
#pragma unroll
                    for (int nt = 0; nt < 4; nt++) {
                        int n = wn * 32 + nt * 8 + grp;   // h index
                        bv[nt][0] = Vt[n * TST + kb + lq];
                        bv[nt][1] = Vt[n * TST + kb + lq + 4];
                    }
#pragma unroll
                    for (int mt = 0; mt < 2; mt++)
#pragma unroll
                        for (int nt = 0; nt < 4; nt++)
                            mma_tf32(o[mt][nt], a[mt], bv[nt]);
                }
            }
            __syncthreads();   // protect Qs/Vt/Ss before next tile load
        }

        // ---- epilogue: divide by l, write out ----
        float* obase = out + ((size_t)b * TT + i0) * HH;
#pragma unroll
        for (int mt = 0; mt < 2; mt++) {
            int m = wm * 32 + mt * 16 + grp;
            const float inv0 = 1.f / l_s[m];
            const float inv1 = 1.f / l_s[m + 8];
#pragma unroll
            for (int nt = 0; nt < 4; nt++) {
                int c = wn * 32 + nt * 8 + 2 * lq;
                *(float2*)&obase[(size_t)m * HH + c] =
                    make_float2(o[mt][nt][0] * inv0, o[mt][nt][1] * inv0);
                *(float2*)&obase[(size_t)(m + 8) * HH + c] =
                    make_float2(o[mt][nt][2] * inv1, o[mt][nt][3] * inv1);
            }
        }
        __syncthreads();   // done with smem before next phase reloads
    }
}

// ---------------------------------------------------------------------------
extern "C" void kernel_launch(void* const* d_in, const int* in_sizes, int n_in,
                              void* d_out, int out_size)
{
    const float* idx = (const float*)d_in[0];
    const float* Wq  = (const float*)d_in[1];
    const float* Wk  = (const float*)d_in[2];
    const float* Wv  = (const float*)d_in[3];
    float* out = (float*)d_out;

    cudaFuncSetAttribute(attn_kernel,
                         cudaFuncAttributeMaxDynamicSharedMemorySize,
                         ATTN_SMEM_BYTES);

    qkv_kernel<<<dim3(NROW / 128, 3), 256>>>(idx, Wq, Wk, Wv);
    attn_kernel<<<dim3(32, BB), 256, ATTN_SMEM_BYTES>>>(out);
}